// round 15
// baseline (speedup 1.0000x reference)
#include <cuda_runtime.h>
#include <cuda_fp16.h>

#define Bn 128
#define Sn 500
#define Dn 32
#define Hn 8
#define HSn 4
#define BHn (Bn*Hn)        // 1024
#define FCIN (Sn*Dn)       // 16000
#define N1 1024
#define KSPLIT 25
#define KSPAN (FCIN/KSPLIT) // 640
#define KCH 32
#define NCHUNK (KSPAN/KCH)  // 20
#define GBUF 20480          // Ah 5120 | Al 5120 | B 10240
#define GEMM_SMEM (2*GBUF)
#define VPITCH 262
#define ASCALE 4096.0f
#define AINV 2.44140625e-4f

typedef unsigned long long u64;

// ---------------- scratch (no allocation allowed) ----------------
__device__ __align__(128) __half g_qh[BHn*Sn*HSn];
__device__ __align__(128) __half g_kh[BHn*Sn*HSn];
__device__ float g_v[BHn*Sn*HSn];
__device__ float g_av[Bn*Sn*Dn];
__device__ __align__(128) __half g_f[(size_t)Bn*FCIN];   // flat, fp16
__device__ float g_part[(size_t)KSPLIT*N1*Bn];   // [ks][n][b]
__device__ float g_y1T[N1*Bn];                   // [n][b]

// ---------------- helpers ----------------
__device__ __forceinline__ unsigned smem_u32(const void* p){ return (unsigned)__cvta_generic_to_shared(p); }
__device__ __forceinline__ void cpasync16(unsigned dst, const void* src){
    asm volatile("cp.async.ca.shared.global [%0], [%1], 16;" :: "r"(dst), "l"(src) : "memory");
}
__device__ __forceinline__ void cpcommit(){ asm volatile("cp.async.commit_group;" ::: "memory"); }
__device__ __forceinline__ void cpwait0(){ asm volatile("cp.async.wait_group 0;" ::: "memory"); }

__device__ __forceinline__ void ldsm4(unsigned* r, unsigned addr){
    asm volatile("ldmatrix.sync.aligned.m8n8.x4.shared.b16 {%0,%1,%2,%3},[%4];"
        : "=r"(r[0]),"=r"(r[1]),"=r"(r[2]),"=r"(r[3]) : "r"(addr));
}
// m16n8k16 fp16 MMA, f32 accumulator
__device__ __forceinline__ void mma16816h(float* d, const unsigned* a, const unsigned* b){
    asm volatile("mma.sync.aligned.m16n8k16.row.col.f32.f16.f16.f32 "
        "{%0,%1,%2,%3},{%4,%5,%6,%7},{%8,%9},{%0,%1,%2,%3};"
        : "+f"(d[0]),"+f"(d[1]),"+f"(d[2]),"+f"(d[3])
        : "r"(a[0]),"r"(a[1]),"r"(a[2]),"r"(a[3]),"r"(b[0]),"r"(b[1]));
}
__device__ __forceinline__ void mma_qk(unsigned& d0, unsigned& d1, unsigned a0, unsigned a1, unsigned b){
    asm("mma.sync.aligned.m16n8k8.row.col.f16.f16.f16.f16 {%0,%1},{%2,%3},{%4},{%5,%6};"
        : "=r"(d0),"=r"(d1) : "r"(a0),"r"(a1),"r"(b),"r"(0u),"r"(0u));
}
__device__ __forceinline__ void mma_pv(float* d, unsigned a0, unsigned a1, unsigned b){
    asm("mma.sync.aligned.m16n8k8.row.col.f32.f16.f16.f32 {%0,%1,%2,%3},{%4,%5},{%6},{%0,%1,%2,%3};"
        : "+f"(d[0]),"+f"(d[1]),"+f"(d[2]),"+f"(d[3]) : "r"(a0),"r"(a1),"r"(b));
}
__device__ __forceinline__ unsigned ex2h2(unsigned x){
    unsigned r; asm("ex2.approx.f16x2 %0,%1;" : "=r"(r) : "r"(x)); return r;
}
__device__ __forceinline__ unsigned pkh2(float lo, float hi){
    __half2 t = __floats2half2_rn(lo,hi);
    return *(unsigned*)&t;
}

#define QSCALE 0.72134752044448169f   // (1/sqrt(4)) * log2(e), folded into q

// ================= K1: QKV projection; q,k stored fp16 (bit-identical to at-use cvt) ===
__global__ __launch_bounds__(256) void k_qkv(const float* __restrict__ x,
    const float* __restrict__ Wq, const float* __restrict__ bq,
    const float* __restrict__ Wk, const float* __restrict__ bk,
    const float* __restrict__ Wv, const float* __restrict__ bv)
{
    __shared__ float ws[3*1056];
    __shared__ float bs[3*32];
    __shared__ float xs[8*32];
    int tid = threadIdx.x;
    for(int i=tid;i<1024;i+=256){
        int ch=i>>5, k=i&31; int d=ch*33+k;
        ws[d]=Wq[i]; ws[1056+d]=Wk[i]; ws[2112+d]=Wv[i];
    }
    if(tid<32){ bs[tid]=bq[tid]; bs[32+tid]=bk[tid]; bs[64+tid]=bv[tid]; }
    int row0 = blockIdx.x*8;
    xs[tid]=x[row0*32+tid];
    __syncthreads();
    #pragma unroll
    for(int t=0;t<3;t++){
        int o = tid + t*256;
        int row = o/96; int cc = o - row*96;
        int which = cc>>5; int ch = cc&31;
        const float* w  = ws + which*1056 + ch*33;
        const float* xr = xs + row*32;
        float sum = bs[which*32+ch];
        #pragma unroll
        for(int i=0;i<32;i++) sum += xr[i]*w[i];
        int gr = row0+row; int b = gr/Sn; int s = gr - b*Sn;
        int idx = ((b*Hn + (ch>>2))*Sn + s)*HSn + (ch&3);
        if(which==0)      g_qh[idx] = __float2half_rn(sum*QSCALE);
        else if(which==1) g_kh[idx] = __float2half_rn(sum);
        else              g_v[idx] = sum;
    }
}

// ================= K2: attention fp16 MMA, 1024 blocks x 256 thr ==========
__global__ __launch_bounds__(256) void k_attn()
{
    __shared__ unsigned ksm[1008];          // [504 j][2 k-pairs] fp16x2
    __shared__ unsigned vhs[5*VPITCH];      // [vn 0..4][252 j-pairs] (vn=4 -> ones)
    __shared__ unsigned vls[5*VPITCH];
    int tid=threadIdx.x, wid=tid>>5, lane=tid&31;
    int bh=blockIdx.x;
    int base=bh*Sn*HSn;
    int base2=bh*Sn*2;                      // u32-pair index into g_kh/g_qh
    const unsigned* kp=(const unsigned*)g_kh;
    const unsigned* qp=(const unsigned*)g_qh;

    for(int i=tid;i<1008;i+=256){
        int j=i>>1;
        ksm[i] = (j<Sn)? kp[base2+i] : 0u;
    }
    for(int i=tid;i<5*252;i+=256){
        int vn=i/252, c=i-vn*252;
        int j0=c*2, j1=j0+1;
        float f0,f1;
        if(vn<4){
            f0 = (j0<Sn)? g_v[base+j0*4+vn] : 0.f;
            f1 = (j1<Sn)? g_v[base+j1*4+vn] : 0.f;
        } else { f0 = (j0<Sn)?1.f:0.f; f1 = (j1<Sn)?1.f:0.f; }
        __half h0=__float2half_rn(f0), h1=__float2half_rn(f1);
        __half2 hh=__halves2half2(h0,h1);
        vhs[vn*VPITCH+c]=*(unsigned*)&hh;
        vls[vn*VPITCH+c]=pkh2(f0-__half2float(h0), f1-__half2float(h1));
    }
    __syncthreads();

    int rr = lane>>2, qc=(lane&3)*2;
    int rowBase = wid*64;
    unsigned qf[4][2];
    #pragma unroll
    for(int mt=0;mt<4;mt++){
        #pragma unroll
        for(int hf=0;hf<2;hf++){
            int row = rowBase + mt*16 + rr + hf*8;
            qf[mt][hf] = (qc<4 && row<Sn) ? qp[base2 + row*2 + (qc>>1)] : 0u;
        }
    }

    float av[4][4];
    #pragma unroll
    for(int mt=0;mt<4;mt++){ av[mt][0]=av[mt][1]=av[mt][2]=av[mt][3]=0.f; }

    int kh = lane&3;
    int jn = lane>>2;
    int vn = lane>>2;
    int vc = lane&3;
    bool kvalid = (kh<2);
    bool vvalid = (vn<5);

    for(int j8=0;j8<63;j8++){
        int jb=j8*8;
        unsigned kf = kvalid ? ksm[(jb+jn)*2+kh] : 0u;
        unsigned vh = vvalid ? vhs[vn*VPITCH + (jb>>1)+vc] : 0u;
        unsigned vl = vvalid ? vls[vn*VPITCH + (jb>>1)+vc] : 0u;
        #pragma unroll
        for(int mt=0;mt<4;mt++){
            unsigned s0,s1;
            mma_qk(s0,s1, qf[mt][0], qf[mt][1], kf);
            unsigned p0 = ex2h2(s0);
            unsigned p1 = ex2h2(s1);
            mma_pv(av[mt], p0,p1, vh);
            mma_pv(av[mt], p0,p1, vl);
        }
    }

    int b=bh>>3, h=bh&7;
    #pragma unroll
    for(int mt=0;mt<4;mt++){
        float den0 = __shfl_sync(0xffffffffu, av[mt][0], (lane & ~3) | 2);
        float den1 = __shfl_sync(0xffffffffu, av[mt][2], (lane & ~3) | 2);
        float i0 = 1.f/den0, i1 = 1.f/den1;
        int row = rowBase + mt*16 + rr;
        if(qc<4){
            if(row < Sn){
                float2 o; o.x=av[mt][0]*i0; o.y=av[mt][1]*i0;
                *(float2*)(g_av + b*(Sn*Dn) + row*Dn + h*4 + qc) = o;
            }
            if(row+8 < Sn){
                float2 o; o.x=av[mt][2]*i1; o.y=av[mt][3]*i1;
                *(float2*)(g_av + b*(Sn*Dn) + (row+8)*Dn + h*4 + qc) = o;
            }
        }
    }
}

// ================= K3: Wo projection -> flat fp16 [b][k] =================
__global__ __launch_bounds__(256) void k_proj(const float* __restrict__ Wo,
                                              const float* __restrict__ bo)
{
    __shared__ float avs[128*33];
    __shared__ float wosT[1024];   // [k][ch]
    __shared__ float bos[32];
    int tid=threadIdx.x; int s=blockIdx.x;
    for(int i=tid;i<1024;i+=256){ int k=i>>5, ch=i&31; wosT[i]=Wo[ch*32+k]; }
    if(tid<32) bos[tid]=bo[tid];
    for(int i=tid;i<4096;i+=256){ int bb=i>>5, c=i&31; avs[bb*33+c]=g_av[bb*(Sn*Dn)+s*Dn+c]; }
    __syncthreads();
    #pragma unroll
    for(int t=0;t<16;t++){
        int o=tid+t*256; int c=o&31, bb=o>>5;
        const float* av=avs+bb*33;
        float sum=bos[c];
        #pragma unroll
        for(int i=0;i<32;i++) sum+=av[i]*wosT[i*32+c];
        g_f[(size_t)bb*FCIN + s*32 + c] = __float2half_rn(sum);
    }
}

// ================= K4: FC1 GEMM v5: A scaled fp16 hi/lo (exact), B fp16 single =======
// grid (16,25), 128 thr. Per warp-kstep: 10 LDSM, 32 MMA (2 per (mt,nt)).
// acc = sum (Ah+Al)*B = 4096 * true; epilogue scales by 2^-12.
__global__ __launch_bounds__(128) void k_gemm(const float* __restrict__ W1)
{
    extern __shared__ __align__(16) char dsm[];
    int tid=threadIdx.x, wid=tid>>5, lane=tid&31;
    int m0 = blockIdx.x*64;
    int ks = blockIdx.y;
    int kbase = ks*KSPAN;
    unsigned smb = smem_u32(dsm);

    float acc[4][4][4];
    #pragma unroll
    for(int i=0;i<4;i++)
        #pragma unroll
        for(int j=0;j<4;j++)
            #pragma unroll
            for(int q=0;q<4;q++) acc[i][j][q]=0.f;

    const char* fp =(const char*)g_f;

    int aR = tid>>1, aC = (tid&1)*16;
    const float* aPtr = W1 + (size_t)(m0+aR)*FCIN + kbase + aC;
    size_t soB0 = ((size_t)tid*FCIN + kbase)*2;

    float areg[16];
    #pragma unroll
    for(int j=0;j<4;j++) *(float4*)(areg+j*4) = *(const float4*)(aPtr + j*4);
    {
        unsigned dst = smb + 10240;
        #pragma unroll
        for(int c=0;c<4;c++)
            cpasync16(dst + tid*80 + c*16, fp + soB0 + c*16);
        cpcommit();
    }

    for(int t=0;t<NCHUNK;t++){
        cpwait0();
        __syncthreads();
        {
            unsigned h[8], l[8];
            #pragma unroll
            for(int i=0;i<8;i++){
                float a0=areg[2*i]*ASCALE, a1=areg[2*i+1]*ASCALE;
                __half h0=__float2half_rn(a0), h1=__float2half_rn(a1);
                __half2 hh=__halves2half2(h0,h1);
                h[i]=*(unsigned*)&hh;
                l[i]=pkh2(a0-__half2float(h0), a1-__half2float(h1));
            }
            char* hb = dsm + (t&1)*GBUF + aR*80 + aC*2;
            ((uint4*)hb)[0] = make_uint4(h[0],h[1],h[2],h[3]);
            ((uint4*)(hb+16))[0] = make_uint4(h[4],h[5],h[6],h[7]);
            char* lb = hb + 5120;
            ((uint4*)lb)[0] = make_uint4(l[0],l[1],l[2],l[3]);
            ((uint4*)(lb+16))[0] = make_uint4(l[4],l[5],l[6],l[7]);
        }
        if(t+1<NCHUNK){
            const float* ap = aPtr + (t+1)*KCH;
            #pragma unroll
            for(int j=0;j<4;j++) *(float4*)(areg+j*4) = *(const float4*)(ap + j*4);
            unsigned dst = smb + ((t+1)&1)*GBUF + 10240;
            size_t soB = soB0 + (size_t)(t+1)*KCH*2;
            #pragma unroll
            for(int c=0;c<4;c++)
                cpasync16(dst + tid*80 + c*16, fp + soB + c*16);
            cpcommit();
        }
        __syncthreads();
        unsigned ubuf = smb + (t&1)*GBUF;
        #pragma unroll
        for(int kstep=0;kstep<2;kstep++){
            unsigned aAddr = ubuf + kstep*32 + (lane&15)*80 + (lane>>4)*16;
            unsigned ah[4][4], al[4][4];
            #pragma unroll
            for(int mt=0;mt<4;mt++){
                ldsm4(ah[mt], aAddr + mt*16*80);
                ldsm4(al[mt], aAddr + 5120 + mt*16*80);
            }
            unsigned bAddr = ubuf + 10240 + kstep*32
                           + (wid*32 + (lane>>4)*8 + (lane&7))*80 + ((lane>>3)&1)*16;
            unsigned bh[2][4];
            #pragma unroll
            for(int g=0;g<2;g++) ldsm4(bh[g], bAddr + g*16*80);
            #pragma unroll
            for(int mt=0;mt<4;mt++)
                #pragma unroll
                for(int nt=0;nt<4;nt++){
                    const unsigned* bp=&bh[nt>>1][(nt&1)*2];
                    mma16816h(acc[mt][nt], ah[mt], bp);
                    mma16816h(acc[mt][nt], al[mt], bp);
                }
        }
    }

    #pragma unroll
    for(int mt=0;mt<4;mt++)
        #pragma unroll
        for(int nt=0;nt<4;nt++){
            int row = m0 + mt*16 + (lane>>2);
            int col = wid*32 + nt*8 + (lane&3)*2;
            float2 v0; v0.x=acc[mt][nt][0]*AINV; v0.y=acc[mt][nt][1]*AINV;
            float2 v1; v1.x=acc[mt][nt][2]*AINV; v1.y=acc[mt][nt][3]*AINV;
            *(float2*)(g_part + ((size_t)ks*N1 + row)*Bn + col) = v0;
            *(float2*)(g_part + ((size_t)ks*N1 + row + 8)*Bn + col) = v1;
        }
}

// ================= K5: split-K reduce + b1 -> y1T[n][b] =================
__global__ __launch_bounds__(256) void k_red(const float* __restrict__ b1)
{
    int n = blockIdx.x*2 + (threadIdx.x>>7);
    int b = threadIdx.x&127;
    float s = b1[n];
    #pragma unroll
    for(int ks=0;ks<KSPLIT;ks++) s += g_part[((size_t)ks*N1+n)*Bn + b];
    g_y1T[n*Bn+b] = s;
}

// ================= K6: FC2 + FC3 =================
__global__ __launch_bounds__(256) void k_fc23(
    const float* __restrict__ W2, const float* __restrict__ b2,
    const float* __restrict__ W3, const float* __restrict__ b3,
    float* __restrict__ dout)
{
    __shared__ float y1[1024];
    __shared__ float w2s[64*64];
    __shared__ float partial[4*64];
    __shared__ float out1s[64];
    int tid=threadIdx.x; int b=blockIdx.x;
    for(int n=tid;n<1024;n+=256) y1[n]=g_y1T[n*Bn+b];
    int o=tid&63, part=tid>>6;
    float acc=0.f;
    for(int chunk=0;chunk<16;chunk++){
        int kbase=chunk*64;
        __syncthreads();
        #pragma unroll
        for(int i=0;i<4;i++){
            int lin=tid+i*256; int row=lin>>4, col4=lin&15;
            float4 f=*(const float4*)(W2 + row*1024 + kbase + col4*4);
            w2s[(col4*4+0)*64+row]=f.x;
            w2s[(col4*4+1)*64+row]=f.y;
            w2s[(col4*4+2)*64+row]=f.z;
            w2s[(col4*4+3)*64+row]=f.w;
        }
        __syncthreads();
        #pragma unroll
        for(int i=0;i<16;i++){
            int k=part*16+i;
            acc += y1[kbase+k]*w2s[k*64+o];
        }
    }
    partial[part*64+o]=acc;
    __syncthreads();
    if(tid<64){
        float v=partial[tid]+partial[64+tid]+partial[128+tid]+partial[192+tid]+b2[tid];
        out1s[tid]=v;
        dout[b*64+tid]=v;
    }
    __syncthreads();
    if(tid<2){
        float s=b3[tid];
        #pragma unroll
        for(int k=0;k<64;k++) s+=out1s[k]*W3[tid*64+k];
        dout[Bn*64 + b*2 + tid]=s;
    }
}

// ================= launch =================
extern "C" void kernel_launch(void* const* d_in, const int* in_sizes, int n_in,
                              void* d_out, int out_size)
{
    const float* x =(const float*)d_in[0];
    const float* Wq=(const float*)d_in[1];  const float* bq=(const float*)d_in[2];
    const float* Wk=(const float*)d_in[3];  const float* bk=(const float*)d_in[4];
    const float* Wv=(const float*)d_in[5];  const float* bv=(const float*)d_in[6];
    const float* Wo=(const float*)d_in[7];  const float* bo=(const float*)d_in[8];
    const float* W1=(const float*)d_in[9];  const float* b1=(const float*)d_in[10];
    const float* W2=(const float*)d_in[11]; const float* b2=(const float*)d_in[12];
    const float* W3=(const float*)d_in[13]; const float* b3=(const float*)d_in[14];
    float* out=(float*)d_out;

    static int smemSet = 0;
    if(!smemSet){
        cudaFuncSetAttribute(k_gemm, cudaFuncAttributeMaxDynamicSharedMemorySize, GEMM_SMEM);
        smemSet = 1;
    }

    k_qkv <<<(Bn*Sn)/8, 256>>>(x,Wq,bq,Wk,bk,Wv,bv);
    k_attn<<<BHn, 256>>>();
    k_proj<<<Sn, 256>>>(Wo,bo);
    k_gemm<<<dim3(16,KSPLIT), 128, GEMM_SMEM>>>(W1);   // 4th launch -> profiled
    k_red <<<N1/2, 256>>>(b1);
    k_fc23<<<Bn, 256>>>(W2,b2,W3,b3,out);
}

// round 16
// speedup vs baseline: 1.3490x; 1.3490x over previous
#include <cuda_runtime.h>
#include <cuda_bf16.h>
#include <cuda_fp16.h>

#define Bn 128
#define Sn 500
#define Dn 32
#define Hn 8
#define HSn 4
#define BHn (Bn*Hn)        // 1024
#define FCIN (Sn*Dn)       // 16000
#define N1 1024
#define KSPLIT 25
#define KSPAN (FCIN/KSPLIT) // 640
#define KCH 32
#define NCHUNK (KSPAN/KCH)  // 20
#define GBUF 30720          // Ah 5120 | Al 5120 | Bh 10240 | Bl 10240
#define GEMM_SMEM (2*GBUF)
#define VPITCH 262          // u32 pitch: (262 mod 32)=6 -> banks 6*vn+c distinct for vn<5

typedef unsigned long long u64;

// ---------------- scratch (no allocation allowed) ----------------
__device__ float g_q[BHn*Sn*HSn];
__device__ float g_k[BHn*Sn*HSn];
__device__ float g_v[BHn*Sn*HSn];
__device__ float g_av[Bn*Sn*Dn];
__device__ __align__(128) __nv_bfloat16 g_fh[(size_t)Bn*FCIN];
__device__ __align__(128) __nv_bfloat16 g_fl[(size_t)Bn*FCIN];
__device__ float g_part[(size_t)KSPLIT*N1*Bn];   // [ks][n(1024)][b(128)]
__device__ float g_y1T[N1*Bn];                   // [n][b]

// ---------------- helpers ----------------
__device__ __forceinline__ unsigned smem_u32(const void* p){ return (unsigned)__cvta_generic_to_shared(p); }
__device__ __forceinline__ void cpasync16(unsigned dst, const void* src){
    asm volatile("cp.async.ca.shared.global [%0], [%1], 16;" :: "r"(dst), "l"(src) : "memory");
}
__device__ __forceinline__ void cpcommit(){ asm volatile("cp.async.commit_group;" ::: "memory"); }
__device__ __forceinline__ void cpwait0(){ asm volatile("cp.async.wait_group 0;" ::: "memory"); }

__device__ __forceinline__ void ldsm4(unsigned* r, unsigned addr){
    asm volatile("ldmatrix.sync.aligned.m8n8.x4.shared.b16 {%0,%1,%2,%3},[%4];"
        : "=r"(r[0]),"=r"(r[1]),"=r"(r[2]),"=r"(r[3]) : "r"(addr));
}
__device__ __forceinline__ void mma16816(float* d, const unsigned* a, const unsigned* b){
    asm volatile("mma.sync.aligned.m16n8k16.row.col.f32.bf16.bf16.f32 "
        "{%0,%1,%2,%3},{%4,%5,%6,%7},{%8,%9},{%0,%1,%2,%3};"
        : "+f"(d[0]),"+f"(d[1]),"+f"(d[2]),"+f"(d[3])
        : "r"(a[0]),"r"(a[1]),"r"(a[2]),"r"(a[3]),"r"(b[0]),"r"(b[1]));
}
// m16n8k8 fp16 MMA, f16 accumulator (C = 0)
__device__ __forceinline__ void mma_qk(unsigned& d0, unsigned& d1, unsigned a0, unsigned a1, unsigned b){
    asm("mma.sync.aligned.m16n8k8.row.col.f16.f16.f16.f16 {%0,%1},{%2,%3},{%4},{%5,%6};"
        : "=r"(d0),"=r"(d1) : "r"(a0),"r"(a1),"r"(b),"r"(0u),"r"(0u));
}
// m16n8k8 fp16 MMA, f32 accumulator
__device__ __forceinline__ void mma_pv(float* d, unsigned a0, unsigned a1, unsigned b){
    asm("mma.sync.aligned.m16n8k8.row.col.f32.f16.f16.f32 {%0,%1,%2,%3},{%4,%5},{%6},{%0,%1,%2,%3};"
        : "+f"(d[0]),"+f"(d[1]),"+f"(d[2]),"+f"(d[3]) : "r"(a0),"r"(a1),"r"(b));
}
__device__ __forceinline__ unsigned ex2h2(unsigned x){
    unsigned r; asm("ex2.approx.f16x2 %0,%1;" : "=r"(r) : "r"(x)); return r;
}
// pack two f32 -> bf16x2 (first arg in low half)
__device__ __forceinline__ unsigned cvt2(float lo, float hi){
    unsigned r; asm("cvt.rn.bf16x2.f32 %0,%1,%2;" : "=r"(r) : "f"(hi),"f"(lo)); return r;
}
__device__ __forceinline__ unsigned pkbf(__nv_bfloat16 l, __nv_bfloat16 h){
    __nv_bfloat162 t = __halves2bfloat162(l,h);
    return *(unsigned*)&t;
}
__device__ __forceinline__ unsigned pkh2(float lo, float hi){
    __half2 t = __floats2half2_rn(lo,hi);
    return *(unsigned*)&t;
}

#define QSCALE 0.72134752044448169f   // (1/sqrt(4)) * log2(e), folded into q

// ================= K1: QKV projection (conflict-free padded weights) =================
__global__ __launch_bounds__(256) void k_qkv(const float* __restrict__ x,
    const float* __restrict__ Wq, const float* __restrict__ bq,
    const float* __restrict__ Wk, const float* __restrict__ bk,
    const float* __restrict__ Wv, const float* __restrict__ bv)
{
    __shared__ float ws[3*1056];
    __shared__ float bs[3*32];
    __shared__ float xs[8*32];
    int tid = threadIdx.x;
    for(int i=tid;i<1024;i+=256){
        int ch=i>>5, k=i&31; int d=ch*33+k;
        ws[d]=Wq[i]; ws[1056+d]=Wk[i]; ws[2112+d]=Wv[i];
    }
    if(tid<32){ bs[tid]=bq[tid]; bs[32+tid]=bk[tid]; bs[64+tid]=bv[tid]; }
    int row0 = blockIdx.x*8;
    xs[tid]=x[row0*32+tid];
    __syncthreads();
    #pragma unroll
    for(int t=0;t<3;t++){
        int o = tid + t*256;
        int row = o/96; int cc = o - row*96;
        int which = cc>>5; int ch = cc&31;
        const float* w  = ws + which*1056 + ch*33;
        const float* xr = xs + row*32;
        float sum = bs[which*32+ch];
        #pragma unroll
        for(int i=0;i<32;i++) sum += xr[i]*w[i];
        int gr = row0+row; int b = gr/Sn; int s = gr - b*Sn;
        int idx = ((b*Hn + (ch>>2))*Sn + s)*HSn + (ch&3);
        if(which==0)      g_q[idx] = sum*QSCALE;
        else if(which==1) g_k[idx] = sum;
        else              g_v[idx] = sum;
    }
}

// ================= K2: attention fp16 MMA, 1024 blocks x 256 thr ==========
// 8 warps, each owns 64 rows = 4 m16 tiles. K/V filled once per bh.
__global__ __launch_bounds__(256) void k_attn()
{
    __shared__ unsigned ksm[1008];          // [504 j][2 k-pairs] fp16x2
    __shared__ unsigned vhs[5*VPITCH];      // [vn 0..4][252 j-pairs] (vn=4 -> ones)
    __shared__ unsigned vls[5*VPITCH];
    int tid=threadIdx.x, wid=tid>>5, lane=tid&31;
    int bh=blockIdx.x;
    int base=bh*Sn*HSn;

    for(int i=tid;i<1008;i+=256){
        int j=i>>1, h=i&1;
        unsigned val=0;
        if(j<Sn) val = pkh2(g_k[base+j*4+h*2], g_k[base+j*4+h*2+1]);
        ksm[i]=val;
    }
    for(int i=tid;i<5*252;i+=256){
        int vn=i/252, c=i-vn*252;
        int j0=c*2, j1=j0+1;
        float f0,f1;
        if(vn<4){
            f0 = (j0<Sn)? g_v[base+j0*4+vn] : 0.f;
            f1 = (j1<Sn)? g_v[base+j1*4+vn] : 0.f;
        } else { f0 = (j0<Sn)?1.f:0.f; f1 = (j1<Sn)?1.f:0.f; }
        __half h0=__float2half_rn(f0), h1=__float2half_rn(f1);
        __half2 hh=__halves2half2(h0,h1);
        vhs[vn*VPITCH+c]=*(unsigned*)&hh;
        vls[vn*VPITCH+c]=pkh2(f0-__half2float(h0), f1-__half2float(h1));
    }
    __syncthreads();

    int rr = lane>>2, qc=(lane&3)*2;
    int rowBase = wid*64;
    unsigned qf[4][2];
    #pragma unroll
    for(int mt=0;mt<4;mt++){
        #pragma unroll
        for(int hf=0;hf<2;hf++){
            int row = rowBase + mt*16 + rr + hf*8;
            float f0=0.f, f1=0.f;
            if(qc<4 && row<Sn){ f0=g_q[base+row*4+qc]; f1=g_q[base+row*4+qc+1]; }
            qf[mt][hf]=pkh2(f0,f1);
        }
    }

    float av[4][4];
    #pragma unroll
    for(int mt=0;mt<4;mt++){ av[mt][0]=av[mt][1]=av[mt][2]=av[mt][3]=0.f; }

    int kh = lane&3;            // k-pair selector (valid <2)
    int jn = lane>>2;           // K frag j index
    int vn = lane>>2;           // V frag output dim (valid <5)
    int vc = lane&3;            // V frag j-pair offset
    bool kvalid = (kh<2);
    bool vvalid = (vn<5);

    for(int j8=0;j8<63;j8++){
        int jb=j8*8;
        unsigned kf = kvalid ? ksm[(jb+jn)*2+kh] : 0u;
        unsigned vh = vvalid ? vhs[vn*VPITCH + (jb>>1)+vc] : 0u;
        unsigned vl = vvalid ? vls[vn*VPITCH + (jb>>1)+vc] : 0u;
        #pragma unroll
        for(int mt=0;mt<4;mt++){
            unsigned s0,s1;
            mma_qk(s0,s1, qf[mt][0], qf[mt][1], kf);
            unsigned p0 = ex2h2(s0);
            unsigned p1 = ex2h2(s1);
            mma_pv(av[mt], p0,p1, vh);
            mma_pv(av[mt], p0,p1, vl);
        }
    }

    int b=bh>>3, h=bh&7;
    #pragma unroll
    for(int mt=0;mt<4;mt++){
        float den0 = __shfl_sync(0xffffffffu, av[mt][0], (lane & ~3) | 2);
        float den1 = __shfl_sync(0xffffffffu, av[mt][2], (lane & ~3) | 2);
        float i0 = 1.f/den0, i1 = 1.f/den1;
        int row = rowBase + mt*16 + rr;
        if(qc<4){
            if(row < Sn){
                float2 o; o.x=av[mt][0]*i0; o.y=av[mt][1]*i0;
                *(float2*)(g_av + b*(Sn*Dn) + row*Dn + h*4 + qc) = o;
            }
            if(row+8 < Sn){
                float2 o; o.x=av[mt][2]*i1; o.y=av[mt][3]*i1;
                *(float2*)(g_av + b*(Sn*Dn) + (row+8)*Dn + h*4 + qc) = o;
            }
        }
    }
}

// ================= K3: Wo projection -> flat bf16 hi/lo [b][k] =================
__global__ __launch_bounds__(256) void k_proj(const float* __restrict__ Wo,
                                              const float* __restrict__ bo)
{
    __shared__ float avs[128*33];
    __shared__ float wosT[1024];   // [k][ch]
    __shared__ float bos[32];
    int tid=threadIdx.x; int s=blockIdx.x;
    for(int i=tid;i<1024;i+=256){ int k=i>>5, ch=i&31; wosT[i]=Wo[ch*32+k]; }
    if(tid<32) bos[tid]=bo[tid];
    for(int i=tid;i<4096;i+=256){ int bb=i>>5, c=i&31; avs[bb*33+c]=g_av[bb*(Sn*Dn)+s*Dn+c]; }
    __syncthreads();
    #pragma unroll
    for(int t=0;t<16;t++){
        int o=tid+t*256; int c=o&31, bb=o>>5;
        const float* av=avs+bb*33;
        float sum=bos[c];
        #pragma unroll
        for(int i=0;i<32;i++) sum+=av[i]*wosT[i*32+c];
        __nv_bfloat16 h=__float2bfloat16(sum);
        __nv_bfloat16 l=__float2bfloat16(sum-__bfloat162float(h));
        size_t k=(size_t)bb*FCIN + s*32 + c;
        g_fh[k]=h; g_fl[k]=l;
    }
}

// ================= K4: FC1 via mma.sync bf16 (hi/lo split, split-K) =================
// W1 converted f32->bf16 hi/lo IN-KERNEL: LDG f32 -> reg -> bf16 STS.
__global__ __launch_bounds__(128) void k_gemm(const float* __restrict__ W1)
{
    extern __shared__ __align__(16) char dsm[];
    int tid=threadIdx.x, wid=tid>>5, lane=tid&31;
    int m0 = blockIdx.x*64;
    int ks = blockIdx.y;
    int kbase = ks*KSPAN;
    unsigned smb = smem_u32(dsm);

    float acc[4][4][4];
    #pragma unroll
    for(int i=0;i<4;i++)
        #pragma unroll
        for(int j=0;j<4;j++)
            #pragma unroll
            for(int q=0;q<4;q++) acc[i][j][q]=0.f;

    const char* fh =(const char*)g_fh;  const char* fl =(const char*)g_fl;

    int aR = tid>>1, aC = (tid&1)*16;
    const float* aPtr = W1 + (size_t)(m0+aR)*FCIN + kbase + aC;
    size_t soB0 = ((size_t)tid*FCIN + kbase)*2;

    float areg[16];
    #pragma unroll
    for(int j=0;j<4;j++) *(float4*)(areg+j*4) = *(const float4*)(aPtr + j*4);
    {
        unsigned dst = smb;
        #pragma unroll
        for(int c=0;c<4;c++){
            cpasync16(dst + 10240 + tid*80 + c*16, fh + soB0 + c*16);
            cpasync16(dst + 20480 + tid*80 + c*16, fl + soB0 + c*16);
        }
        cpcommit();
    }

    for(int t=0;t<NCHUNK;t++){
        cpwait0();
        __syncthreads();
        {
            unsigned hi[8], lo[8];
            #pragma unroll
            for(int i=0;i<8;i++){
                float f0=areg[2*i], f1=areg[2*i+1];
                __nv_bfloat16 h0=__float2bfloat16(f0), h1=__float2bfloat16(f1);
                hi[i]=pkbf(h0,h1);
                lo[i]=cvt2(f0-__bfloat162float(h0), f1-__bfloat162float(h1));
            }
            char* hb = dsm + (t&1)*GBUF + aR*80 + aC*2;
            ((uint4*)hb)[0] = make_uint4(hi[0],hi[1],hi[2],hi[3]);
            ((uint4*)(hb+16))[0] = make_uint4(hi[4],hi[5],hi[6],hi[7]);
            char* lb = hb + 5120;
            ((uint4*)lb)[0] = make_uint4(lo[0],lo[1],lo[2],lo[3]);
            ((uint4*)(lb+16))[0] = make_uint4(lo[4],lo[5],lo[6],lo[7]);
        }
        if(t+1<NCHUNK){
            const float* ap = aPtr + (t+1)*KCH;
            #pragma unroll
            for(int j=0;j<4;j++) *(float4*)(areg+j*4) = *(const float4*)(ap + j*4);
            unsigned dst = smb + ((t+1)&1)*GBUF;
            size_t soB = soB0 + (size_t)(t+1)*KCH*2;
            #pragma unroll
            for(int c=0;c<4;c++){
                cpasync16(dst + 10240 + tid*80 + c*16, fh + soB + c*16);
                cpasync16(dst + 20480 + tid*80 + c*16, fl + soB + c*16);
            }
            cpcommit();
        }
        __syncthreads();
        unsigned ubuf = smb + (t&1)*GBUF;
        #pragma unroll
        for(int kstep=0;kstep<2;kstep++){
            unsigned aAddr = ubuf + kstep*32 + (lane&15)*80 + (lane>>4)*16;
            unsigned ah[4][4], al[4][4];
            #pragma unroll
            for(int mt=0;mt<4;mt++){
                ldsm4(ah[mt], aAddr + mt*16*80);
                ldsm4(al[mt], aAddr + 5120 + mt*16*80);
            }
            unsigned bAddr = ubuf + 10240 + kstep*32
                           + (wid*32 + (lane>>4)*8 + (lane&7))*80 + ((lane>>3)&1)*16;
            unsigned bh[2][4], bl[2][4];
            #pragma unroll
            for(int g=0;g<2;g++){
                ldsm4(bh[g], bAddr + g*16*80);
                ldsm4(bl[g], bAddr + 10240 + g*16*80);
            }
            #pragma unroll
            for(int mt=0;mt<4;mt++)
                #pragma unroll
                for(int nt=0;nt<4;nt++){
                    const unsigned* bhf=&bh[nt>>1][(nt&1)*2];
                    const unsigned* blf=&bl[nt>>1][(nt&1)*2];
                    mma16816(acc[mt][nt], ah[mt], bhf);
                    mma16816(acc[mt][nt], ah[mt], blf);
                    mma16816(acc[mt][nt], al[mt], bhf);
                }
        }
    }

    #pragma unroll
    for(int mt=0;mt<4;mt++)
        #pragma unroll
        for(int nt=0;nt<4;nt++){
            int row = m0 + mt*16 + (lane>>2);
            int col = wid*32 + nt*8 + (lane&3)*2;
            float2 v0; v0.x=acc[mt][nt][0]; v0.y=acc[mt][nt][1];
            float2 v1; v1.x=acc[mt][nt][2]; v1.y=acc[mt][nt][3];
            *(float2*)(g_part + ((size_t)ks*N1 + row)*Bn + col) = v0;
            *(float2*)(g_part + ((size_t)ks*N1 + row + 8)*Bn + col) = v1;
        }
}

// ================= K5: split-K reduce + b1 -> y1T[n][b] (float4) =================
__global__ __launch_bounds__(256) void k_red(const float* __restrict__ b1)
{
    int n = blockIdx.x*8 + (threadIdx.x>>5);       // 128 blocks x 8 rows
    int b4 = (threadIdx.x&31)*4;
    float4 s = make_float4(b1[n],b1[n],b1[n],b1[n]);
    s.y=s.x; s.z=s.x; s.w=s.x;
    float4 acc = make_float4(b1[n],b1[n],b1[n],b1[n]);
    acc.x=b1[n]; acc.y=b1[n]; acc.z=b1[n]; acc.w=b1[n];
    float4 r = make_float4(b1[n], b1[n], b1[n], b1[n]);
    #pragma unroll
    for(int ks=0;ks<KSPLIT;ks++){
        float4 p = *(const float4*)(g_part + ((size_t)ks*N1+n)*Bn + b4);
        r.x+=p.x; r.y+=p.y; r.z+=p.z; r.w+=p.w;
    }
    *(float4*)(g_y1T + n*Bn + b4) = r;
}

// ================= K6: FC2 + FC3 =================
__global__ __launch_bounds__(256) void k_fc23(
    const float* __restrict__ W2, const float* __restrict__ b2,
    const float* __restrict__ W3, const float* __restrict__ b3,
    float* __restrict__ dout)
{
    __shared__ float y1[1024];
    __shared__ float w2s[64*64];
    __shared__ float partial[4*64];
    __shared__ float out1s[64];
    int tid=threadIdx.x; int b=blockIdx.x;
    for(int n=tid;n<1024;n+=256) y1[n]=g_y1T[n*Bn+b];
    int o=tid&63, part=tid>>6;
    float acc=0.f;
    for(int chunk=0;chunk<16;chunk++){
        int kbase=chunk*64;
        __syncthreads();
        #pragma unroll
        for(int i=0;i<4;i++){
            int lin=tid+i*256; int row=lin>>4, col4=lin&15;
            float4 f=*(const float4*)(W2 + row*1024 + kbase + col4*4);
            w2s[(col4*4+0)*64+row]=f.x;
            w2s[(col4*4+1)*64+row]=f.y;
            w2s[(col4*4+2)*64+row]=f.z;
            w2s[(col4*4+3)*64+row]=f.w;
        }
        __syncthreads();
        #pragma unroll
        for(int i=0;i<16;i++){
            int k=part*16+i;
            acc += y1[kbase+k]*w2s[k*64+o];
        }
    }
    partial[part*64+o]=acc;
    __syncthreads();
    if(tid<64){
        float v=partial[tid]+partial[64+tid]+partial[128+tid]+partial[192+tid]+b2[tid];
        out1s[tid]=v;
        dout[b*64+tid]=v;
    }
    __syncthreads();
    if(tid<2){
        float s=b3[tid];
        #pragma unroll
        for(int k=0;k<64;k++) s+=out1s[k]*W3[tid*64+k];
        dout[Bn*64 + b*2 + tid]=s;
    }
}

// ================= launch =================
extern "C" void kernel_launch(void* const* d_in, const int* in_sizes, int n_in,
                              void* d_out, int out_size)
{
    const float* x =(const float*)d_in[0];
    const float* Wq=(const float*)d_in[1];  const float* bq=(const float*)d_in[2];
    const float* Wk=(const float*)d_in[3];  const float* bk=(const float*)d_in[4];
    const float* Wv=(const float*)d_in[5];  const float* bv=(const float*)d_in[6];
    const float* Wo=(const float*)d_in[7];  const float* bo=(const float*)d_in[8];
    const float* W1=(const float*)d_in[9];  const float* b1=(const float*)d_in[10];
    const float* W2=(const float*)d_in[11]; const float* b2=(const float*)d_in[12];
    const float* W3=(const float*)d_in[13]; const float* b3=(const float*)d_in[14];
    float* out=(float*)d_out;

    static int smemSet = 0;
    if(!smemSet){
        cudaFuncSetAttribute(k_gemm, cudaFuncAttributeMaxDynamicSharedMemorySize, GEMM_SMEM);
        smemSet = 1;
    }

    k_qkv <<<(Bn*Sn)/8, 256>>>(x,Wq,bq,Wk,bk,Wv,bv);
    k_attn<<<BHn, 256>>>();
    k_proj<<<Sn, 256>>>(Wo,bo);
    k_gemm<<<dim3(16,KSPLIT), 128, GEMM_SMEM>>>(W1);   // 4th launch -> profiled
    k_red <<<N1/8, 256>>>(b1);
    k_fc23<<<Bn, 256>>>(W2,b2,W3,b3,out);
}

// round 17
// speedup vs baseline: 1.5125x; 1.1212x over previous
#include <cuda_runtime.h>
#include <cuda_bf16.h>
#include <cuda_fp16.h>

#define Bn 128
#define Sn 500
#define Dn 32
#define Hn 8
#define HSn 4
#define BHn (Bn*Hn)        // 1024
#define FCIN (Sn*Dn)       // 16000
#define N1 1024
#define KSPLIT 25
#define KSPAN (FCIN/KSPLIT) // 640
#define KCH 32
#define NCHUNK (KSPAN/KCH)  // 20
#define GBUF 30720          // Ah 5120 | Al 5120 | Bh 10240 | Bl 10240
#define GEMM_SMEM (2*GBUF)
#define VPITCH 262          // u32 pitch: (262 mod 32)=6 -> banks 6*vn+c distinct for vn<5

typedef unsigned long long u64;

// ---------------- scratch (no allocation allowed) ----------------
__device__ float g_q[BHn*Sn*HSn];
__device__ float g_k[BHn*Sn*HSn];
__device__ float g_v[BHn*Sn*HSn];
__device__ float g_av[Bn*Sn*Dn];
__device__ __align__(128) __nv_bfloat16 g_fh[(size_t)Bn*FCIN];
__device__ __align__(128) __nv_bfloat16 g_fl[(size_t)Bn*FCIN];
__device__ float g_part[(size_t)KSPLIT*N1*Bn];   // [ks][n(1024)][b(128)]
__device__ float g_y1T[N1*Bn];                   // [n][b]

// ---------------- helpers ----------------
__device__ __forceinline__ unsigned smem_u32(const void* p){ return (unsigned)__cvta_generic_to_shared(p); }
__device__ __forceinline__ void cpasync16(unsigned dst, const void* src){
    asm volatile("cp.async.ca.shared.global [%0], [%1], 16;" :: "r"(dst), "l"(src) : "memory");
}
__device__ __forceinline__ void cpcommit(){ asm volatile("cp.async.commit_group;" ::: "memory"); }
__device__ __forceinline__ void cpwait0(){ asm volatile("cp.async.wait_group 0;" ::: "memory"); }

__device__ __forceinline__ void ldsm4(unsigned* r, unsigned addr){
    asm volatile("ldmatrix.sync.aligned.m8n8.x4.shared.b16 {%0,%1,%2,%3},[%4];"
        : "=r"(r[0]),"=r"(r[1]),"=r"(r[2]),"=r"(r[3]) : "r"(addr));
}
__device__ __forceinline__ void mma16816(float* d, const unsigned* a, const unsigned* b){
    asm volatile("mma.sync.aligned.m16n8k16.row.col.f32.bf16.bf16.f32 "
        "{%0,%1,%2,%3},{%4,%5,%6,%7},{%8,%9},{%0,%1,%2,%3};"
        : "+f"(d[0]),"+f"(d[1]),"+f"(d[2]),"+f"(d[3])
        : "r"(a[0]),"r"(a[1]),"r"(a[2]),"r"(a[3]),"r"(b[0]),"r"(b[1]));
}
// m16n8k8 fp16 MMA, f16 accumulator (C = 0)
__device__ __forceinline__ void mma_qk(unsigned& d0, unsigned& d1, unsigned a0, unsigned a1, unsigned b){
    asm("mma.sync.aligned.m16n8k8.row.col.f16.f16.f16.f16 {%0,%1},{%2,%3},{%4},{%5,%6};"
        : "=r"(d0),"=r"(d1) : "r"(a0),"r"(a1),"r"(b),"r"(0u),"r"(0u));
}
// m16n8k8 fp16 MMA, f32 accumulator
__device__ __forceinline__ void mma_pv(float* d, unsigned a0, unsigned a1, unsigned b){
    asm("mma.sync.aligned.m16n8k8.row.col.f32.f16.f16.f32 {%0,%1,%2,%3},{%4,%5},{%6},{%0,%1,%2,%3};"
        : "+f"(d[0]),"+f"(d[1]),"+f"(d[2]),"+f"(d[3]) : "r"(a0),"r"(a1),"r"(b));
}
__device__ __forceinline__ unsigned ex2h2(unsigned x){
    unsigned r; asm("ex2.approx.f16x2 %0,%1;" : "=r"(r) : "r"(x)); return r;
}
// pack two f32 -> bf16x2 (first arg in low half)
__device__ __forceinline__ unsigned cvt2(float lo, float hi){
    unsigned r; asm("cvt.rn.bf16x2.f32 %0,%1,%2;" : "=r"(r) : "f"(hi),"f"(lo)); return r;
}
__device__ __forceinline__ unsigned pkbf(__nv_bfloat16 l, __nv_bfloat16 h){
    __nv_bfloat162 t = __halves2bfloat162(l,h);
    return *(unsigned*)&t;
}
__device__ __forceinline__ unsigned pkh2(float lo, float hi){
    __half2 t = __floats2half2_rn(lo,hi);
    return *(unsigned*)&t;
}

#define QSCALE 0.72134752044448169f   // (1/sqrt(4)) * log2(e), folded into q

// ================= K1: QKV projection v2 =================
// 500 blocks x 128 thr, thread owns one row: x in regs, weights via broadcast LDS.128
// (pad 36 floats/row -> 16B aligned), fully coalesced float4 stores.
__global__ __launch_bounds__(128) void k_qkv(const float* __restrict__ x,
    const float* __restrict__ Wq, const float* __restrict__ bq,
    const float* __restrict__ Wk, const float* __restrict__ bk,
    const float* __restrict__ Wv, const float* __restrict__ bv)
{
    __shared__ __align__(16) float ws[3*1152];   // [which][ch][36]
    __shared__ float bs[96];
    int tid = threadIdx.x;
    for(int idx=tid; idx<3072; idx+=128){
        int which=idx>>10, rem=idx&1023;
        int ch=rem>>5, i=rem&31;
        const float* W = (which==0)?Wq:((which==1)?Wk:Wv);
        ws[which*1152 + ch*36 + i] = W[rem];
    }
    if(tid<96){
        const float* B = (tid<32)?bq:((tid<64)?bk:bv);
        bs[tid] = B[tid&31];
    }
    __syncthreads();
    int r = blockIdx.x*128 + tid;
    int b = r/Sn, s = r - b*Sn;
    float xv[32];
    const float4* xr = (const float4*)(x + (size_t)r*32);
    #pragma unroll
    for(int j=0;j<8;j++) *(float4*)(xv+j*4) = xr[j];
    #pragma unroll 1
    for(int which=0;which<3;which++){
        float* dst = (which==0)?g_q:((which==1)?g_k:g_v);
        #pragma unroll 1
        for(int h=0;h<8;h++){
            float o4[4];
            #pragma unroll
            for(int sub=0;sub<4;sub++){
                int ch=h*4+sub;
                const float* w = ws + which*1152 + ch*36;
                float acc = bs[which*32+ch];
                #pragma unroll
                for(int j=0;j<8;j++){
                    float4 wv = *(const float4*)(w + j*4);
                    acc += xv[j*4+0]*wv.x + xv[j*4+1]*wv.y
                         + xv[j*4+2]*wv.z + xv[j*4+3]*wv.w;
                }
                o4[sub] = (which==0)? acc*QSCALE : acc;
            }
            *(float4*)(dst + ((size_t)(b*Hn+h)*Sn + s)*4)
                = make_float4(o4[0],o4[1],o4[2],o4[3]);
        }
    }
}

// ================= K2: attention fp16 MMA, 1024 blocks x 256 thr ==========
__global__ __launch_bounds__(256) void k_attn()
{
    __shared__ unsigned ksm[1008];          // [504 j][2 k-pairs] fp16x2
    __shared__ unsigned vhs[5*VPITCH];      // [vn 0..4][252 j-pairs] (vn=4 -> ones)
    __shared__ unsigned vls[5*VPITCH];
    int tid=threadIdx.x, wid=tid>>5, lane=tid&31;
    int bh=blockIdx.x;
    int base=bh*Sn*HSn;

    for(int i=tid;i<1008;i+=256){
        int j=i>>1, h=i&1;
        unsigned val=0;
        if(j<Sn) val = pkh2(g_k[base+j*4+h*2], g_k[base+j*4+h*2+1]);
        ksm[i]=val;
    }
    for(int i=tid;i<5*252;i+=256){
        int vn=i/252, c=i-vn*252;
        int j0=c*2, j1=j0+1;
        float f0,f1;
        if(vn<4){
            f0 = (j0<Sn)? g_v[base+j0*4+vn] : 0.f;
            f1 = (j1<Sn)? g_v[base+j1*4+vn] : 0.f;
        } else { f0 = (j0<Sn)?1.f:0.f; f1 = (j1<Sn)?1.f:0.f; }
        __half h0=__float2half_rn(f0), h1=__float2half_rn(f1);
        __half2 hh=__halves2half2(h0,h1);
        vhs[vn*VPITCH+c]=*(unsigned*)&hh;
        vls[vn*VPITCH+c]=pkh2(f0-__half2float(h0), f1-__half2float(h1));
    }
    __syncthreads();

    int rr = lane>>2, qc=(lane&3)*2;
    int rowBase = wid*64;
    unsigned qf[4][2];
    #pragma unroll
    for(int mt=0;mt<4;mt++){
        #pragma unroll
        for(int hf=0;hf<2;hf++){
            int row = rowBase + mt*16 + rr + hf*8;
            float f0=0.f, f1=0.f;
            if(qc<4 && row<Sn){ f0=g_q[base+row*4+qc]; f1=g_q[base+row*4+qc+1]; }
            qf[mt][hf]=pkh2(f0,f1);
        }
    }

    float av[4][4];
    #pragma unroll
    for(int mt=0;mt<4;mt++){ av[mt][0]=av[mt][1]=av[mt][2]=av[mt][3]=0.f; }

    int kh = lane&3;
    int jn = lane>>2;
    int vn = lane>>2;
    int vc = lane&3;
    bool kvalid = (kh<2);
    bool vvalid = (vn<5);

    for(int j8=0;j8<63;j8++){
        int jb=j8*8;
        unsigned kf = kvalid ? ksm[(jb+jn)*2+kh] : 0u;
        unsigned vh = vvalid ? vhs[vn*VPITCH + (jb>>1)+vc] : 0u;
        unsigned vl = vvalid ? vls[vn*VPITCH + (jb>>1)+vc] : 0u;
        #pragma unroll
        for(int mt=0;mt<4;mt++){
            unsigned s0,s1;
            mma_qk(s0,s1, qf[mt][0], qf[mt][1], kf);
            unsigned p0 = ex2h2(s0);
            unsigned p1 = ex2h2(s1);
            mma_pv(av[mt], p0,p1, vh);
            mma_pv(av[mt], p0,p1, vl);
        }
    }

    int b=bh>>3, h=bh&7;
    #pragma unroll
    for(int mt=0;mt<4;mt++){
        float den0 = __shfl_sync(0xffffffffu, av[mt][0], (lane & ~3) | 2);
        float den1 = __shfl_sync(0xffffffffu, av[mt][2], (lane & ~3) | 2);
        float i0 = 1.f/den0, i1 = 1.f/den1;
        int row = rowBase + mt*16 + rr;
        if(qc<4){
            if(row < Sn){
                float2 o; o.x=av[mt][0]*i0; o.y=av[mt][1]*i0;
                *(float2*)(g_av + b*(Sn*Dn) + row*Dn + h*4 + qc) = o;
            }
            if(row+8 < Sn){
                float2 o; o.x=av[mt][2]*i1; o.y=av[mt][3]*i1;
                *(float2*)(g_av + b*(Sn*Dn) + (row+8)*Dn + h*4 + qc) = o;
            }
        }
    }
}

// ================= K3: Wo projection v2 -> flat bf16 hi/lo [b][k] =================
// 500 blocks x 128 thr. Lane owns batch row (av in regs), broadcast float4 weights.
__global__ __launch_bounds__(128) void k_proj(const float* __restrict__ Wo,
                                              const float* __restrict__ bo)
{
    __shared__ __align__(16) float wos[32*36];   // [c][36]
    __shared__ float bos[32];
    int tid=threadIdx.x; int s=blockIdx.x;
    for(int idx=tid; idx<1024; idx+=128){
        int c=idx>>5, i=idx&31;
        wos[c*36+i] = Wo[idx];
    }
    if(tid<32) bos[tid]=bo[tid];
    __syncthreads();
    float av[32];
    const float4* ar = (const float4*)(g_av + (size_t)tid*(Sn*Dn) + s*Dn);
    #pragma unroll
    for(int j=0;j<8;j++) *(float4*)(av+j*4)=ar[j];
    size_t obase = (size_t)tid*FCIN + s*32;
    #pragma unroll 1
    for(int cc=0;cc<4;cc++){
        unsigned h4[4], l4[4];
        #pragma unroll
        for(int u=0;u<4;u++){
            float acc2[2];
            #pragma unroll
            for(int e=0;e<2;e++){
                int c=cc*8+u*2+e;
                const float* w = wos + c*36;
                float acc=bos[c];
                #pragma unroll
                for(int j=0;j<8;j++){
                    float4 wv=*(const float4*)(w+j*4);
                    acc += av[j*4+0]*wv.x + av[j*4+1]*wv.y
                         + av[j*4+2]*wv.z + av[j*4+3]*wv.w;
                }
                acc2[e]=acc;
            }
            __nv_bfloat16 b0=__float2bfloat16(acc2[0]), b1=__float2bfloat16(acc2[1]);
            h4[u]=pkbf(b0,b1);
            l4[u]=cvt2(acc2[0]-__bfloat162float(b0), acc2[1]-__bfloat162float(b1));
        }
        *(uint4*)(g_fh+obase+cc*8)=make_uint4(h4[0],h4[1],h4[2],h4[3]);
        *(uint4*)(g_fl+obase+cc*8)=make_uint4(l4[0],l4[1],l4[2],l4[3]);
    }
}

// ================= K4: FC1 via mma.sync bf16 (hi/lo split, split-K) =================
__global__ __launch_bounds__(128) void k_gemm(const float* __restrict__ W1)
{
    extern __shared__ __align__(16) char dsm[];
    int tid=threadIdx.x, wid=tid>>5, lane=tid&31;
    int m0 = blockIdx.x*64;
    int ks = blockIdx.y;
    int kbase = ks*KSPAN;
    unsigned smb = smem_u32(dsm);

    float acc[4][4][4];
    #pragma unroll
    for(int i=0;i<4;i++)
        #pragma unroll
        for(int j=0;j<4;j++)
            #pragma unroll
            for(int q=0;q<4;q++) acc[i][j][q]=0.f;

    const char* fh =(const char*)g_fh;  const char* fl =(const char*)g_fl;

    int aR = tid>>1, aC = (tid&1)*16;
    const float* aPtr = W1 + (size_t)(m0+aR)*FCIN + kbase + aC;
    size_t soB0 = ((size_t)tid*FCIN + kbase)*2;

    float areg[16];
    #pragma unroll
    for(int j=0;j<4;j++) *(float4*)(areg+j*4) = *(const float4*)(aPtr + j*4);
    {
        unsigned dst = smb;
        #pragma unroll
        for(int c=0;c<4;c++){
            cpasync16(dst + 10240 + tid*80 + c*16, fh + soB0 + c*16);
            cpasync16(dst + 20480 + tid*80 + c*16, fl + soB0 + c*16);
        }
        cpcommit();
    }

    for(int t=0;t<NCHUNK;t++){
        cpwait0();
        __syncthreads();
        {
            unsigned hi[8], lo[8];
            #pragma unroll
            for(int i=0;i<8;i++){
                float f0=areg[2*i], f1=areg[2*i+1];
                __nv_bfloat16 h0=__float2bfloat16(f0), h1=__float2bfloat16(f1);
                hi[i]=pkbf(h0,h1);
                lo[i]=cvt2(f0-__bfloat162float(h0), f1-__bfloat162float(h1));
            }
            char* hb = dsm + (t&1)*GBUF + aR*80 + aC*2;
            ((uint4*)hb)[0] = make_uint4(hi[0],hi[1],hi[2],hi[3]);
            ((uint4*)(hb+16))[0] = make_uint4(hi[4],hi[5],hi[6],hi[7]);
            char* lb = hb + 5120;
            ((uint4*)lb)[0] = make_uint4(lo[0],lo[1],lo[2],lo[3]);
            ((uint4*)(lb+16))[0] = make_uint4(lo[4],lo[5],lo[6],lo[7]);
        }
        if(t+1<NCHUNK){
            const float* ap = aPtr + (t+1)*KCH;
            #pragma unroll
            for(int j=0;j<4;j++) *(float4*)(areg+j*4) = *(const float4*)(ap + j*4);
            unsigned dst = smb + ((t+1)&1)*GBUF;
            size_t soB = soB0 + (size_t)(t+1)*KCH*2;
            #pragma unroll
            for(int c=0;c<4;c++){
                cpasync16(dst + 10240 + tid*80 + c*16, fh + soB + c*16);
                cpasync16(dst + 20480 + tid*80 + c*16, fl + soB + c*16);
            }
            cpcommit();
        }
        __syncthreads();
        unsigned ubuf = smb + (t&1)*GBUF;
        #pragma unroll
        for(int kstep=0;kstep<2;kstep++){
            unsigned aAddr = ubuf + kstep*32 + (lane&15)*80 + (lane>>4)*16;
            unsigned ah[4][4], al[4][4];
            #pragma unroll
            for(int mt=0;mt<4;mt++){
                ldsm4(ah[mt], aAddr + mt*16*80);
                ldsm4(al[mt], aAddr + 5120 + mt*16*80);
            }
            unsigned bAddr = ubuf + 10240 + kstep*32
                           + (wid*32 + (lane>>4)*8 + (lane&7))*80 + ((lane>>3)&1)*16;
            unsigned bh[2][4], bl[2][4];
            #pragma unroll
            for(int g=0;g<2;g++){
                ldsm4(bh[g], bAddr + g*16*80);
                ldsm4(bl[g], bAddr + 10240 + g*16*80);
            }
            #pragma unroll
            for(int mt=0;mt<4;mt++)
                #pragma unroll
                for(int nt=0;nt<4;nt++){
                    const unsigned* bhf=&bh[nt>>1][(nt&1)*2];
                    const unsigned* blf=&bl[nt>>1][(nt&1)*2];
                    mma16816(acc[mt][nt], ah[mt], bhf);
                    mma16816(acc[mt][nt], ah[mt], blf);
                    mma16816(acc[mt][nt], al[mt], bhf);
                }
        }
    }

    #pragma unroll
    for(int mt=0;mt<4;mt++)
        #pragma unroll
        for(int nt=0;nt<4;nt++){
            int row = m0 + mt*16 + (lane>>2);
            int col = wid*32 + nt*8 + (lane&3)*2;
            float2 v0; v0.x=acc[mt][nt][0]; v0.y=acc[mt][nt][1];
            float2 v1; v1.x=acc[mt][nt][2]; v1.y=acc[mt][nt][3];
            *(float2*)(g_part + ((size_t)ks*N1 + row)*Bn + col) = v0;
            *(float2*)(g_part + ((size_t)ks*N1 + row + 8)*Bn + col) = v1;
        }
}

// ================= K5: split-K reduce + b1 -> y1T[n][b] (float4) =================
__global__ __launch_bounds__(256) void k_red(const float* __restrict__ b1)
{
    int n = blockIdx.x*8 + (threadIdx.x>>5);       // 128 blocks x 8 rows
    int b4 = (threadIdx.x&31)*4;
    float4 r = make_float4(b1[n], b1[n], b1[n], b1[n]);
    #pragma unroll
    for(int ks=0;ks<KSPLIT;ks++){
        float4 p = *(const float4*)(g_part + ((size_t)ks*N1+n)*Bn + b4);
        r.x+=p.x; r.y+=p.y; r.z+=p.z; r.w+=p.w;
    }
    *(float4*)(g_y1T + n*Bn + b4) = r;
}

// ================= K6: FC2 + FC3 =================
__global__ __launch_bounds__(256) void k_fc23(
    const float* __restrict__ W2, const float* __restrict__ b2,
    const float* __restrict__ W3, const float* __restrict__ b3,
    float* __restrict__ dout)
{
    __shared__ float y1[1024];
    __shared__ float w2s[64*64];
    __shared__ float partial[4*64];
    __shared__ float out1s[64];
    int tid=threadIdx.x; int b=blockIdx.x;
    for(int n=tid;n<1024;n+=256) y1[n]=g_y1T[n*Bn+b];
    int o=tid&63, part=tid>>6;
    float acc=0.f;
    for(int chunk=0;chunk<16;chunk++){
        int kbase=chunk*64;
        __syncthreads();
        #pragma unroll
        for(int i=0;i<4;i++){
            int lin=tid+i*256; int row=lin>>4, col4=lin&15;
            float4 f=*(const float4*)(W2 + row*1024 + kbase + col4*4);
            w2s[(col4*4+0)*64+row]=f.x;
            w2s[(col4*4+1)*64+row]=f.y;
            w2s[(col4*4+2)*64+row]=f.z;
            w2s[(col4*4+3)*64+row]=f.w;
        }
        __syncthreads();
        #pragma unroll
        for(int i=0;i<16;i++){
            int k=part*16+i;
            acc += y1[kbase+k]*w2s[k*64+o];
        }
    }
    partial[part*64+o]=acc;
    __syncthreads();
    if(tid<64){
        float v=partial[tid]+partial[64+tid]+partial[128+tid]+partial[192+tid]+b2[tid];
        out1s[tid]=v;
        dout[b*64+tid]=v;
    }
    __syncthreads();
    if(tid<2){
        float s=b3[tid];
        #pragma unroll
        for(int k=0;k<64;k++) s+=out1s[k]*W3[tid*64+k];
        dout[Bn*64 + b*2 + tid]=s;
    }
}

// ================= launch =================
extern "C" void kernel_launch(void* const* d_in, const int* in_sizes, int n_in,
                              void* d_out, int out_size)
{
    const float* x =(const float*)d_in[0];
    const float* Wq=(const float*)d_in[1];  const float* bq=(const float*)d_in[2];
    const float* Wk=(const float*)d_in[3];  const float* bk=(const float*)d_in[4];
    const float* Wv=(const float*)d_in[5];  const float* bv=(const float*)d_in[6];
    const float* Wo=(const float*)d_in[7];  const float* bo=(const float*)d_in[8];
    const float* W1=(const float*)d_in[9];  const float* b1=(const float*)d_in[10];
    const float* W2=(const float*)d_in[11]; const float* b2=(const float*)d_in[12];
    const float* W3=(const float*)d_in[13]; const float* b3=(const float*)d_in[14];
    float* out=(float*)d_out;

    static int smemSet = 0;
    if(!smemSet){
        cudaFuncSetAttribute(k_gemm, cudaFuncAttributeMaxDynamicSharedMemorySize, GEMM_SMEM);
        smemSet = 1;
    }

    k_qkv <<<500, 128>>>(x,Wq,bq,Wk,bk,Wv,bv);
    k_attn<<<BHn, 256>>>();
    k_proj<<<Sn, 128>>>(Wo,bo);
    k_gemm<<<dim3(16,KSPLIT), 128, GEMM_SMEM>>>(W1);   // 4th launch -> profiled
    k_red <<<N1/8, 256>>>(b1);
    k_fc23<<<Bn, 256>>>(W2,b2,W3,b3,out);
}